// round 1
// baseline (speedup 1.0000x reference)
#include <cuda_runtime.h>
#include <cstdint>

// TropicalLinear forward on GB300:
//   out[n,o] = max_i( x[n,i] + w[o,i] ) + bias[o]
// (the STE soft term cancels exactly in the forward pass)
//
// Kernel 1: split-K max-plus GEMM, 128 CTAs (8 o-tiles x 2 n-tiles x 8 k-splits),
//           partial maxes into __device__ scratch.
// Kernel 2: reduce 8 partials + bias into d_out.

#define N_ROWS  128
#define IN_DIM  1024
#define OUT_DIM 1024
#define SPLIT   8
#define KC      (IN_DIM / SPLIT)   // 128 k per CTA
#define KS      64                 // smem stage depth (2 stages per CTA)
#define TN      64                 // n-tile
#define TO      128                // o-tile

// 8 * 128 * 1024 floats = 4 MB static scratch (allocation-free rule)
__device__ float g_part[SPLIT * N_ROWS * OUT_DIM];

__device__ __forceinline__ float neg_inf() { return __int_as_float(0xff800000); }

__global__ __launch_bounds__(256, 1)
void tropical_main_kernel(const float* __restrict__ x,
                          const float* __restrict__ w)
{
    // 16 KB + 32 KB = 48 KB static shared (at the limit, by design)
    __shared__ float xs[KS][TN];
    __shared__ float ws[KS][TO];

    const int tid  = threadIdx.x;
    const int tx   = tid & 15;       // o-direction (16 threads)
    const int ty   = tid >> 4;       // n-direction (16 threads)
    const int warp = tid >> 5;
    const int lane = tid & 31;

    const int o0 = blockIdx.x * TO;
    const int n0 = blockIdx.y * TN;
    const int k0 = blockIdx.z * KC;

    float acc[4][8];
#pragma unroll
    for (int i = 0; i < 4; ++i)
#pragma unroll
        for (int j = 0; j < 8; ++j)
            acc[i][j] = neg_inf();

#pragma unroll
    for (int stage = 0; stage < KC / KS; ++stage) {
        const int kbase = k0 + stage * KS;

        // ---- stage tiles into smem, transposed to k-major ----
        // Each warp owns k-groups {warp, warp+8} (4 floats each). Lanes span
        // rows, so the transposing STS hits 32 distinct banks (conflict-free).
#pragma unroll
        for (int g = 0; g < 2; ++g) {
            const int kk = (warp + g * 8) * 4;
            // x tile: 64 rows x KS cols
#pragma unroll
            for (int rr = 0; rr < 2; ++rr) {
                const int row = lane + rr * 32;
                float4 v = *(const float4*)(x + (size_t)(n0 + row) * IN_DIM + kbase + kk);
                xs[kk + 0][row] = v.x;
                xs[kk + 1][row] = v.y;
                xs[kk + 2][row] = v.z;
                xs[kk + 3][row] = v.w;
            }
            // w tile: 128 rows x KS cols
#pragma unroll
            for (int rr = 0; rr < 4; ++rr) {
                const int row = lane + rr * 32;
                float4 v = *(const float4*)(w + (size_t)(o0 + row) * IN_DIM + kbase + kk);
                ws[kk + 0][row] = v.x;
                ws[kk + 1][row] = v.y;
                ws[kk + 2][row] = v.z;
                ws[kk + 3][row] = v.w;
            }
        }
        __syncthreads();

        // ---- compute: 4n x 8o register tile, max-plus over k ----
#pragma unroll 8
        for (int k = 0; k < KS; ++k) {
            float4 xv4 = *(const float4*)&xs[k][ty * 4];
            float4 wa4 = *(const float4*)&ws[k][tx * 4];
            float4 wb4 = *(const float4*)&ws[k][64 + tx * 4];
            float xv[4] = {xv4.x, xv4.y, xv4.z, xv4.w};
            float wv[8] = {wa4.x, wa4.y, wa4.z, wa4.w,
                           wb4.x, wb4.y, wb4.z, wb4.w};
#pragma unroll
            for (int i = 0; i < 4; ++i)
#pragma unroll
                for (int j = 0; j < 8; ++j)
                    acc[i][j] = fmaxf(acc[i][j], xv[i] + wv[j]);
        }
        __syncthreads();
    }

    // ---- write partial maxes ----
    float* base = g_part + (size_t)blockIdx.z * (N_ROWS * OUT_DIM);
#pragma unroll
    for (int i = 0; i < 4; ++i) {
        const int row = n0 + ty * 4 + i;
        float4 a = make_float4(acc[i][0], acc[i][1], acc[i][2], acc[i][3]);
        float4 b = make_float4(acc[i][4], acc[i][5], acc[i][6], acc[i][7]);
        *(float4*)(base + (size_t)row * OUT_DIM + o0 + tx * 4)      = a;
        *(float4*)(base + (size_t)row * OUT_DIM + o0 + 64 + tx * 4) = b;
    }
}

__global__ __launch_bounds__(256, 1)
void tropical_combine_kernel(const float* __restrict__ bias,
                             float* __restrict__ out)
{
    const int idx = blockIdx.x * 256 + threadIdx.x;   // grid covers 131072
    float m = neg_inf();
#pragma unroll
    for (int s = 0; s < SPLIT; ++s)
        m = fmaxf(m, g_part[(size_t)s * (N_ROWS * OUT_DIM) + idx]);
    out[idx] = m + bias[idx & (OUT_DIM - 1)];
}

extern "C" void kernel_launch(void* const* d_in, const int* in_sizes, int n_in,
                              void* d_out, int out_size)
{
    const float* x    = (const float*)d_in[0];   // [128, 1024]
    const float* w    = (const float*)d_in[1];   // [1024, 1024]
    const float* bias = (const float*)d_in[2];   // [1024]
    float* out = (float*)d_out;                  // [128, 1024]

    dim3 grid(OUT_DIM / TO, N_ROWS / TN, SPLIT); // (8, 2, 8) = 128 CTAs
    tropical_main_kernel<<<grid, 256>>>(x, w);

    tropical_combine_kernel<<<(N_ROWS * OUT_DIM) / 256, 256>>>(bias, out);
}

// round 4
// speedup vs baseline: 1.0046x; 1.0046x over previous
#include <cuda_runtime.h>
#include <cstdint>

// TropicalLinear forward on GB300:
//   out[n,o] = max_i( x[n,i] + w[o,i] ) + bias[o]
// (the STE soft term cancels exactly in the forward pass)
//
// R2: 512-thread CTAs (16 warps/SM, 50% occ), 4n x 4o register tile
//     (2 LDS.128 per k per thread), split-K=8 -> 128 CTAs, vectorized combine.

#define N_ROWS  128
#define IN_DIM  1024
#define OUT_DIM 1024
#define SPLIT   8
#define KC      (IN_DIM / SPLIT)   // 128 k per CTA
#define KS      64                 // smem stage depth (2 stages per CTA)
#define TN      64                 // n-tile
#define TO      128                // o-tile

// 8 * 128 * 1024 floats = 4 MB static scratch (allocation-free rule)
__device__ float g_part[SPLIT * N_ROWS * OUT_DIM];

__device__ __forceinline__ float neg_inf() { return __int_as_float(0xff800000); }

__global__ __launch_bounds__(512, 1)
void tropical_main_kernel(const float* __restrict__ x,
                          const float* __restrict__ w)
{
    // 16 KB + 32 KB = 48 KB static shared (exactly at the static limit)
    __shared__ float xs[KS][TN];
    __shared__ float ws[KS][TO];

    const int tid  = threadIdx.x;
    const int tx   = tid & 31;       // o-direction (32 threads x 4 = 128)
    const int ty   = tid >> 5;       // n-direction (16 threads x 4 = 64)
    const int warp = tid >> 5;       // == ty
    const int lane = tid & 31;       // == tx

    const int o0 = blockIdx.x * TO;
    const int n0 = blockIdx.y * TN;
    const int k0 = blockIdx.z * KC;

    float acc[4][4];
#pragma unroll
    for (int i = 0; i < 4; ++i)
#pragma unroll
        for (int j = 0; j < 4; ++j)
            acc[i][j] = neg_inf();

#pragma unroll
    for (int stage = 0; stage < KC / KS; ++stage) {
        const int kbase = k0 + stage * KS;

        // ---- stage tiles into smem, transposed to k-major ----
        // 16 warps, 16 k-groups of 4 k's each: warp owns group `warp`.
        // Lanes span rows; the transposing STS is lane-contiguous (4B stride)
        // so it is conflict-free. LDG is 16B/lane scattered but everything
        // lives in L2 after first touch (total working set 4.5 MB << 126 MB).
        {
            const int kk = warp * 4;
            // x tile: 64 rows x KS cols
#pragma unroll
            for (int rr = 0; rr < 2; ++rr) {
                const int row = lane + rr * 32;
                float4 v = *(const float4*)(x + (size_t)(n0 + row) * IN_DIM + kbase + kk);
                xs[kk + 0][row] = v.x;
                xs[kk + 1][row] = v.y;
                xs[kk + 2][row] = v.z;
                xs[kk + 3][row] = v.w;
            }
            // w tile: 128 rows x KS cols
#pragma unroll
            for (int rr = 0; rr < 4; ++rr) {
                const int row = lane + rr * 32;
                float4 v = *(const float4*)(w + (size_t)(o0 + row) * IN_DIM + kbase + kk);
                ws[kk + 0][row] = v.x;
                ws[kk + 1][row] = v.y;
                ws[kk + 2][row] = v.z;
                ws[kk + 3][row] = v.w;
            }
        }
        __syncthreads();

        // ---- compute: 4n x 4o register tile, max-plus over k ----
        // xv4: one broadcast LDS.128 per warp; wv4: 32 contiguous float4
        // (512 B, 4 clean phases). 2 LDS + 16 FADD + 16 FMNMX per 16 pairs.
#pragma unroll 8
        for (int k = 0; k < KS; ++k) {
            float4 xv4 = *(const float4*)&xs[k][ty * 4];
            float4 wv4 = *(const float4*)&ws[k][tx * 4];
            float xv[4] = {xv4.x, xv4.y, xv4.z, xv4.w};
            float wv[4] = {wv4.x, wv4.y, wv4.z, wv4.w};
#pragma unroll
            for (int i = 0; i < 4; ++i)
#pragma unroll
                for (int j = 0; j < 4; ++j)
                    acc[i][j] = fmaxf(acc[i][j], xv[i] + wv[j]);
        }
        __syncthreads();
    }

    // ---- write partial maxes (coalesced: tx = lane, 512 B per warp) ----
    float* base = g_part + (size_t)blockIdx.z * (N_ROWS * OUT_DIM);
#pragma unroll
    for (int i = 0; i < 4; ++i) {
        const int row = n0 + ty * 4 + i;
        float4 a = make_float4(acc[i][0], acc[i][1], acc[i][2], acc[i][3]);
        *(float4*)(base + (size_t)row * OUT_DIM + o0 + tx * 4) = a;
    }
}

__global__ __launch_bounds__(256, 1)
void tropical_combine_kernel(const float* __restrict__ bias,
                             float* __restrict__ out)
{
    // Each thread reduces 4 consecutive outputs: 8 front-batched LDG.128
    // (MLP=8) instead of 8 scalar strided loads.
    const int idx4 = blockIdx.x * 256 + threadIdx.x;   // 0..32767
    const int base = idx4 * 4;

    float4 m = make_float4(neg_inf(), neg_inf(), neg_inf(), neg_inf());
#pragma unroll
    for (int s = 0; s < SPLIT; ++s) {
        float4 v = *(const float4*)(g_part + (size_t)s * (N_ROWS * OUT_DIM) + base);
        m.x = fmaxf(m.x, v.x);
        m.y = fmaxf(m.y, v.y);
        m.z = fmaxf(m.z, v.z);
        m.w = fmaxf(m.w, v.w);
    }
    float4 b = *(const float4*)(bias + (base & (OUT_DIM - 1)));
    m.x += b.x; m.y += b.y; m.z += b.z; m.w += b.w;
    *(float4*)(out + base) = m;
}

extern "C" void kernel_launch(void* const* d_in, const int* in_sizes, int n_in,
                              void* d_out, int out_size)
{
    const float* x    = (const float*)d_in[0];   // [128, 1024]
    const float* w    = (const float*)d_in[1];   // [1024, 1024]
    const float* bias = (const float*)d_in[2];   // [1024]
    float* out = (float*)d_out;                  // [128, 1024]

    dim3 grid(OUT_DIM / TO, N_ROWS / TN, SPLIT); // (8, 2, 8) = 128 CTAs
    tropical_main_kernel<<<grid, 512>>>(x, w);

    tropical_combine_kernel<<<(N_ROWS * OUT_DIM) / (256 * 4), 256>>>(bias, out);
}